// round 15
// baseline (speedup 1.0000x reference)
#include <cuda_runtime.h>
#include <cuda_bf16.h>
#include <cuda_fp8.h>
#include <math.h>

#define HH 80
#define WW 80
#define NPIX 6400
#define CC 6
#define LL 6
#define CL 36          // LL*CC
#define NPAD 40        // CL padded to 5x n8 (was 48; 4 pad rows only)
#define MT 128         // gemm M-tile (rows of Kb)
#define KSPLIT 10
#define KPART 640      // NPIX/KSPLIT
#define KSTAGE 128     // fp8 elems per stage
#define NSTAGES 5      // KPART/KSTAGE
#define KPB 144        // padded BYTES per smem row (bank-conflict-free)
#define NBE 25         // elbo partial blocks per label
#define RPB 8          // k_Kb rows per block
#define GEMM_SMEM (2 * (MT + NPAD) * KPB)   // 48384 B
// Kb stored as 256*exp(-d/2) (scale folded into exponent). sm8 = 256*sm.
// fb_true = partial/(256 * normb_scaled)
#define INV256 (1.0f / 256.0f)

typedef unsigned long long ull;
typedef unsigned int uint;
typedef unsigned short ushort;
typedef unsigned char uchar;

// ---- scratch (device globals: allocation-free rule; zero-initialized) ----
__device__ __align__(16) __nv_fp8_e4m3 g_Kb8[(size_t)NPIX * NPIX];  // 41 MB bilateral kernel, fp8 (x256)
__device__ __align__(16) __nv_fp8_e4m3 g_SM8[NPAD * NPIX];          // softmax rows fp8 (x256; rows 36..39 stay 0)
__device__ float g_normb[NPIX];           // scaled by 256
__device__ float g_G[HH * HH];            // 1D spatial gaussian (theta_gamma)
__device__ float g_Snorm[HH];
__device__ float4 g_z4[NPIX];             // coords scaled by sqrt(log2e)/theta
__device__ float  g_z1[NPIX];
__device__ float  g_zh[NPIX];             // 0.5*|z'|^2  (= log2e * d-half-norm)
__device__ float g_unary[CC * NPIX];
__device__ float g_SM[CL * NPIX];         // f32 row-major (for conv)
__device__ float g_Fs[CL * NPIX];
__device__ float g_part[(size_t)KSPLIT * NPAD * NPIX];  // split-K partials [ks][r][p]
__device__ float g_As[CC * CC];           // compat @ Wsp
__device__ float g_Ab[CC * CC];           // compat @ Wbl
__device__ float g_epart[LL * NBE];

__device__ __forceinline__ void cp16(void* dst, const void* src) {
    unsigned d = (unsigned)__cvta_generic_to_shared(dst);
    asm volatile("cp.async.cg.shared.global [%0], [%1], 16;" :: "r"(d), "l"(src));
}
__device__ __forceinline__ void mma_fp8(float* d, uint a0, uint a1, uint a2, uint a3,
                                        uint b0, uint b1) {
    asm volatile(
        "mma.sync.aligned.m16n8k32.row.col.f32.e4m3.e4m3.f32 "
        "{%0,%1,%2,%3}, {%4,%5,%6,%7}, {%8,%9}, {%0,%1,%2,%3};"
        : "+f"(d[0]), "+f"(d[1]), "+f"(d[2]), "+f"(d[3])
        : "r"(a0), "r"(a1), "r"(a2), "r"(a3), "r"(b0), "r"(b1));
}
__device__ __forceinline__ void ldsm4(uint& r0, uint& r1, uint& r2, uint& r3, uint addr) {
    asm volatile("ldmatrix.sync.aligned.m8n8.x4.shared.b16 {%0,%1,%2,%3}, [%4];"
                 : "=r"(r0), "=r"(r1), "=r"(r2), "=r"(r3) : "r"(addr));
}
__device__ __forceinline__ void ldsm2(uint& r0, uint& r1, uint addr) {
    asm volatile("ldmatrix.sync.aligned.m8n8.x2.shared.b16 {%0,%1}, [%2];"
                 : "=r"(r0), "=r"(r1) : "r"(addr));
}
__device__ __forceinline__ ushort fp8x2(float hi, float lo) {
    ushort r;
    asm("cvt.rn.satfinite.e4m3x2.f32 %0, %1, %2;" : "=h"(r) : "f"(hi), "f"(lo));
    return r;
}
__device__ __forceinline__ float ex2(float x) {
    float r;
    asm("ex2.approx.f32 %0, %1;" : "=f"(r) : "f"(x));
    return r;
}

// ---- launch 1: prep: log2e-scaled coords + half-norms, unary transpose, iter-1 softmax ----
__global__ void k_prep(const float* __restrict__ unary, const float* __restrict__ feat) {
    int p = blockIdx.x * blockDim.x + threadIdx.x;
    if (p >= NPIX) return;
    int y = p / WW, x = p % WW;
    const float sc = 1.20112240878645f;          // sqrt(log2e)
    const float inva = sc / 8.0f;                // /theta_alpha
    const float invb = sc / 0.15f;               // /theta_beta
    float4 z;
    z.x = (float)y * inva;
    z.y = (float)x * inva;
    z.z = feat[p * 3 + 0] * invb;
    z.w = feat[p * 3 + 1] * invb;
    float z1 = feat[p * 3 + 2] * invb;
    g_z4[p] = z;
    g_z1[p] = z1;
    g_zh[p] = 0.5f * (z.x * z.x + z.y * z.y + z.z * z.z + z.w * z.w + z1 * z1);
    float q[CC], m = -1e30f;
#pragma unroll
    for (int c = 0; c < CC; c++) {
        q[c] = unary[p * CC + c];
        g_unary[c * NPIX + p] = q[c];
        m = fmaxf(m, q[c]);
    }
    float s = 0.f;
#pragma unroll
    for (int c = 0; c < CC; c++) { q[c] = __expf(q[c] - m); s += q[c]; }
    float inv = 1.0f / s;
#pragma unroll
    for (int l = 0; l < LL; l++)
#pragma unroll
        for (int c = 0; c < CC; c++) {
            float v = q[c] * inv;
            g_SM[(l * CC + c) * NPIX + p] = v;
            g_SM8[(l * CC + c) * NPIX + p] = __nv_fp8_e4m3(v * 256.0f);
        }
}

// ---- launch 2: 1D spatial kernel, row sums, fused CxC matrices ----
__global__ void k_prep_small(const float* __restrict__ compat,
                             const float* __restrict__ wsp,
                             const float* __restrict__ wbl) {
    int tid = threadIdx.x;
    for (int i = tid; i < HH * HH; i += blockDim.x) {
        int a = i / HH, b = i % HH;
        float d = (float)(a - b);
        g_G[i] = expf(-d * d * (1.0f / 18.0f));   // 2*theta_gamma^2 = 18
    }
    __syncthreads();
    if (tid < HH) {
        float s = 0.f;
        for (int b = 0; b < HH; b++) s += g_G[tid * HH + b];
        g_Snorm[tid] = s;
    }
    if (tid < CC * CC) {
        int i = tid / CC, j = tid % CC;
        float as = 0.f, ab = 0.f;
        for (int k = 0; k < CC; k++) {
            as += compat[i * CC + k] * wsp[k * CC + j];
            ab += compat[i * CC + k] * wbl[k * CC + j];
        }
        g_As[tid] = as;
        g_Ab[tid] = ab;
    }
}

// ---- fused separable spatial filter: one block per row-slice r ----
__global__ __launch_bounds__(1024) void k_conv() {
    __shared__ float s_in[NPIX];
    __shared__ float s_mid[NPIX];
    int r = blockIdx.x;
    for (int i = threadIdx.x; i < NPIX; i += 1024)
        s_in[i] = g_SM[r * NPIX + i];
    __syncthreads();
    for (int i = threadIdx.x; i < NPIX; i += 1024) {
        int y = i / WW, x2 = i % WW;
        float acc = 0.f;
        const float* row = &s_in[y * WW];
#pragma unroll 8
        for (int x = 0; x < WW; x++) acc += row[x] * g_G[x * HH + x2];
        s_mid[i] = acc;
    }
    __syncthreads();
    for (int i = threadIdx.x; i < NPIX; i += 1024) {
        int y2 = i / WW, x = i % WW;
        float acc = 0.f;
#pragma unroll 8
        for (int y = 0; y < HH; y++) acc += s_mid[y * WW + x] * g_G[y * HH + y2];
        g_Fs[r * NPIX + i] = acc / (g_Snorm[y2] * g_Snorm[x]);
    }
}

// ---- launch 4 (captured): bilateral kernel via MUFU ex2, scale folded into exponent ----
__global__ __launch_bounds__(256) void k_Kb() {
    int i0 = blockIdx.x * RPB;
    __shared__ float4 s_z4[RPB];
    __shared__ float s_z1[RPB], s_zh[RPB];
    if (threadIdx.x < RPB) {
        s_z4[threadIdx.x] = g_z4[i0 + threadIdx.x];
        s_z1[threadIdx.x] = g_z1[i0 + threadIdx.x];
        s_zh[threadIdx.x] = g_zh[i0 + threadIdx.x] - 8.0f;   // -8: fold x256 into ex2
    }
    __syncthreads();
    float4 zi[RPB]; float zi1[RPB], ci[RPB];
#pragma unroll
    for (int r = 0; r < RPB; r++) { zi[r] = s_z4[r]; zi1[r] = s_z1[r]; ci[r] = s_zh[r]; }

    float sum[RPB];
#pragma unroll
    for (int r = 0; r < RPB; r++) sum[r] = 0.f;

    for (int j = threadIdx.x * 2; j < NPIX; j += 512) {
        float4 za = g_z4[j], zb = g_z4[j + 1];
        float z1a = g_z1[j], z1b = g_z1[j + 1];
        float ha = g_zh[j], hb = g_zh[j + 1];
#pragma unroll
        for (int r = 0; r < RPB; r++) {
            float dota = zi[r].x * za.x + zi[r].y * za.y + zi[r].z * za.z
                       + zi[r].w * za.w + zi1[r] * z1a;
            float dotb = zi[r].x * zb.x + zi[r].y * zb.y + zi[r].z * zb.z
                       + zi[r].w * zb.w + zi1[r] * z1b;
            float va = ex2(dota - ci[r] - ha);   // = 256 * exp(-d/2)
            float vb = ex2(dotb - ci[r] - hb);
            *(ushort*)&g_Kb8[(size_t)(i0 + r) * NPIX + j] = fp8x2(vb, va);
            sum[r] += va + vb;
        }
    }
#pragma unroll
    for (int r = 0; r < RPB; r++)
#pragma unroll
        for (int o = 16; o > 0; o >>= 1)
            sum[r] += __shfl_xor_sync(0xffffffffu, sum[r], o);
    __shared__ float wsum[8][RPB];
    int w = threadIdx.x >> 5, lane = threadIdx.x & 31;
    if (lane == 0)
#pragma unroll
        for (int r = 0; r < RPB; r++) wsum[w][r] = sum[r];
    __syncthreads();
    if (threadIdx.x < RPB) {
        float s = 0.f;
#pragma unroll
        for (int w2 = 0; w2 < 8; w2++) s += wsum[w2][threadIdx.x];
        g_normb[i0 + threadIdx.x] = s;           // scaled by 256
    }
}

// ---- FP8 tensor-core GEMM, MT=128, n=40 (2x ldsm4 + 1x ldsm2), 2-stage cp.async ----
__global__ __launch_bounds__(256) void k_gemm() {
    extern __shared__ __align__(16) uchar smem[];
    uchar* As = smem;                        // [2][MT*KPB] bytes
    uchar* Bs = smem + 2 * MT * KPB;         // [2][NPAD*KPB] bytes

    int tid = threadIdx.x, lane = tid & 31, w = tid >> 5;
    int ptile = blockIdx.x * MT;
    int kbase = blockIdx.y * KPART;
    const uchar* Kb = (const uchar*)g_Kb8;
    const uchar* SMb = (const uchar*)g_SM8;

    float d[5][4];
#pragma unroll
    for (int f = 0; f < 5; f++)
#pragma unroll
        for (int j = 0; j < 4; j++) d[f][j] = 0.f;

    auto issue = [&](int bi, int k0) {
        uchar* dA = As + bi * (MT * KPB);
#pragma unroll 1
        for (int f = tid; f < 1024; f += 256) {   // 128 rows x 8 x 16B chunks
            int row = f >> 3, off = f & 7;
            cp16(&dA[row * KPB + off * 16],
                 Kb + (size_t)(ptile + row) * NPIX + k0 + off * 16);
        }
        uchar* dB = Bs + bi * (NPAD * KPB);
#pragma unroll 1
        for (int f = tid; f < 320; f += 256) {    // 40 rows x 8 x 16B chunks
            int row = f >> 3, off = f & 7;
            cp16(&dB[row * KPB + off * 16],
                 SMb + (size_t)row * NPIX + k0 + off * 16);
        }
    };

    issue(0, kbase);
    asm volatile("cp.async.commit_group;");
    issue(1, kbase + KSTAGE);
    asm volatile("cp.async.commit_group;");

    // ldmatrix lane-address offsets (bytes)
    uint offA = (w * 16 + (lane & 15)) * KPB + (lane >> 4) * 16;
    uint offB4[2];
#pragma unroll
    for (int f = 0; f < 2; f++)
        offB4[f] = (16 * f + (lane & 7) + ((lane >> 4) << 3)) * KPB + ((lane >> 3) & 1) * 16;
    uint offB2 = (32 + (lane & 7)) * KPB + ((lane >> 3) & 1) * 16;
    uint baseA = (uint)__cvta_generic_to_shared(As);
    uint baseB = (uint)__cvta_generic_to_shared(Bs);
    const uint strA = MT * KPB, strB = NPAD * KPB;

    for (int t = 0; t < NSTAGES; t++) {
        if (t + 1 < NSTAGES) {
            asm volatile("cp.async.wait_group 1;");
        } else {
            asm volatile("cp.async.wait_group 0;");
        }
        __syncthreads();
        int bi = t & 1;
        uint aP = baseA + bi * strA + offA;
        uint bP = baseB + bi * strB;
#pragma unroll
        for (int j = 0; j < 4; j++) {             // j covers 32 bytes of k
            uint a0, a1, a2, a3;
            ldsm4(a0, a1, a2, a3, aP + j * 32);
#pragma unroll
            for (int f = 0; f < 2; f++) {
                uint b0, b1, b2, b3;
                ldsm4(b0, b1, b2, b3, bP + offB4[f] + j * 32);
                mma_fp8(d[2 * f],     a0, a1, a2, a3, b0, b1);
                mma_fp8(d[2 * f + 1], a0, a1, a2, a3, b2, b3);
            }
            uint c0, c1;
            ldsm2(c0, c1, bP + offB2 + j * 32);
            mma_fp8(d[4], a0, a1, a2, a3, c0, c1);
        }
        __syncthreads();                          // all warps done with buf bi
        if (t + 2 < NSTAGES) {
            issue(bi, kbase + (t + 2) * KSTAGE);  // refill the freed buffer
            asm volatile("cp.async.commit_group;");
        }
    }

    // epilogue: D frag -> g_part[ks][r][p]
    int prow = ptile + w * 16 + (lane >> 2);
    size_t kb = (size_t)blockIdx.y * NPAD * NPIX;
#pragma unroll
    for (int f = 0; f < 5; f++) {
        int rc = f * 8 + (lane & 3) * 2;
        g_part[kb + (size_t)rc * NPIX + prow]           = d[f][0];
        g_part[kb + (size_t)(rc + 1) * NPIX + prow]     = d[f][1];
        g_part[kb + (size_t)rc * NPIX + prow + 8]       = d[f][2];
        g_part[kb + (size_t)(rc + 1) * NPIX + prow + 8] = d[f][3];
    }
}

// ---- fused: split-K reduce + unscale + normalize + q update + softmax ----
__global__ void k_post(const float* __restrict__ lg) {
    int t = blockIdx.x * 256 + threadIdx.x;
    if (t >= LL * NPIX) return;
    int l = t / NPIX, p = t % NPIX;
    float invnb = INV256 / g_normb[p];
    float fs[CC], fb[CC];
#pragma unroll
    for (int c = 0; c < CC; c++) {
        int r = l * CC + c;
        fs[c] = g_Fs[r * NPIX + p];
        float s = 0.f;
#pragma unroll
        for (int ks = 0; ks < KSPLIT; ks++)
            s += g_part[(size_t)ks * NPAD * NPIX + (size_t)r * NPIX + p];
        fb[c] = s * invnb;
    }
    float q[CC], m = -1e30f;
#pragma unroll
    for (int c = 0; c < CC; c++) {
        float pw = 0.f;
#pragma unroll
        for (int k = 0; k < CC; k++)
            pw += g_As[c * CC + k] * fs[k] + g_Ab[c * CC + k] * fb[k];
        q[c] = g_unary[c * NPIX + p] + lg[c * CC + l] - pw;
        m = fmaxf(m, q[c]);
    }
    float s = 0.f;
#pragma unroll
    for (int c = 0; c < CC; c++) { q[c] = __expf(q[c] - m); s += q[c]; }
    float inv = 1.0f / s;
#pragma unroll
    for (int c = 0; c < CC; c++) {
        float v = q[c] * inv;
        g_SM[(l * CC + c) * NPIX + p] = v;
        g_SM8[(l * CC + c) * NPIX + p] = __nv_fp8_e4m3(v * 256.0f);
    }
}

// ---- ELBO partials: grid (25, LL), one pixel per thread ----
__global__ void k_elbo(const float* __restrict__ wsp,
                       const float* __restrict__ wbl,
                       const float* __restrict__ lg) {
    int l = blockIdx.y;
    int p = blockIdx.x * 256 + threadIdx.x;   // 25*256 = NPIX exact
    float acc;
    {
        float invnb = INV256 / g_normb[p];
        float sm[CC], fs[CC], fb[CC];
#pragma unroll
        for (int c = 0; c < CC; c++) {
            int r = l * CC + c;
            sm[c] = g_SM[r * NPIX + p];
            fs[c] = g_Fs[r * NPIX + p];
            float s = 0.f;
#pragma unroll
            for (int ks = 0; ks < KSPLIT; ks++)
                s += g_part[(size_t)ks * NPAD * NPIX + (size_t)r * NPIX + p];
            fb[c] = s * invnb;
        }
        acc = 0.f;
#pragma unroll
        for (int c = 0; c < CC; c++) {
            float msg = 0.f;
#pragma unroll
            for (int k = 0; k < CC; k++)
                msg += wsp[c * CC + k] * fs[k] + wbl[c * CC + k] * fb[k];
            acc += sm[c] * (g_unary[c * NPIX + p] + lg[c * CC + l] - msg)
                 - sm[c] * logf(sm[c] + 1e-10f);
        }
    }
    __shared__ float red[256];
    red[threadIdx.x] = acc;
    __syncthreads();
    for (int s = 128; s > 0; s >>= 1) {
        if (threadIdx.x < s) red[threadIdx.x] += red[threadIdx.x + s];
        __syncthreads();
    }
    if (threadIdx.x == 0) g_epart[l * NBE + blockIdx.x] = red[0];
}

__global__ void k_final(float* __restrict__ out) {
    int l = threadIdx.x;
    if (l < LL) {
        float s = 0.f;
        for (int b = 0; b < NBE; b++) s += g_epart[l * NBE + b];
        out[l] = s;
    }
}

extern "C" void kernel_launch(void* const* d_in, const int* in_sizes, int n_in,
                              void* d_out, int out_size) {
    const float* unary  = (const float*)d_in[0];   // (1,80,80,6)
    const float* feat   = (const float*)d_in[1];   // (80,80,3)
    const float* compat = (const float*)d_in[2];   // (6,6)
    const float* lg     = (const float*)d_in[3];   // (6,6)
    const float* wsp    = (const float*)d_in[4];   // (6,6)
    const float* wbl    = (const float*)d_in[5];   // (6,6)
    float* out = (float*)d_out;

    cudaFuncSetAttribute(k_gemm, cudaFuncAttributeMaxDynamicSharedMemorySize, GEMM_SMEM);

    // launches 1-4: slot 4 = the MUFU k_Kb -> gets the ncu capture
    k_prep<<<25, 256>>>(unary, feat);
    k_prep_small<<<1, 128>>>(compat, wsp, wbl);
    k_conv<<<CL, 1024>>>();                        // pass-1 spatial
    k_Kb<<<NPIX / RPB, 256>>>();                   // CAPTURED
    k_gemm<<<dim3(NPIX / MT, KSPLIT), 256, GEMM_SMEM>>>();   // pass-1 bilateral

    // passes 2..5
    for (int it = 0; it < 4; it++) {
        k_post<<<150, 256>>>(lg);
        k_conv<<<CL, 1024>>>();
        k_gemm<<<dim3(NPIX / MT, KSPLIT), 256, GEMM_SMEM>>>();
    }

    k_elbo<<<dim3(NBE, LL), 256>>>(wsp, wbl, lg);
    k_final<<<1, 32>>>(out);
}

// round 16
// speedup vs baseline: 1.5697x; 1.5697x over previous
#include <cuda_runtime.h>
#include <cuda_bf16.h>
#include <cuda_fp8.h>
#include <math.h>

#define HH 80
#define WW 80
#define NPIX 6400
#define CC 6
#define LL 6
#define CL 36          // LL*CC
#define NPAD 40        // CL padded to 5x n8
#define MT 128         // gemm M-tile (rows of Kb)
#define KSPLIT 10
#define KPART 640      // NPIX/KSPLIT
#define KSTAGE 128     // fp8 elems per stage
#define NSTAGES 5      // KPART/KSTAGE
#define KPB 144        // padded BYTES per smem row (bank-conflict-free)
#define NBE 25         // elbo partial blocks per label
#define RPB 8          // k_Kb rows per block
#define GEMM_SMEM (2 * (MT + NPAD) * KPB)   // 48384 B
// Kb stored as 256*exp(-d/2) (scale folded into exponent). sm8 = 256*sm.
#define INV256 (1.0f / 256.0f)

typedef unsigned long long ull;
typedef unsigned int uint;
typedef unsigned short ushort;
typedef unsigned char uchar;

// ---- scratch (device globals: allocation-free rule; zero-initialized) ----
__device__ __align__(16) __nv_fp8_e4m3 g_Kb8[(size_t)NPIX * NPIX];  // 41 MB bilateral kernel, fp8 (x256)
__device__ __align__(16) __nv_fp8_e4m3 g_SM8[NPAD * NPIX];          // softmax rows fp8 (x256; rows 36..39 stay 0)
__device__ float g_normb[NPIX];           // scaled by 256
__device__ float g_G[HH * HH];            // 1D spatial gaussian (theta_gamma)
__device__ float g_Snorm[HH];
__device__ float4 g_z4[NPIX];             // coords scaled by sqrt(log2e)/theta
__device__ float  g_z1[NPIX];
__device__ float  g_zh[NPIX];             // 0.5*|z'|^2
__device__ float g_unary[CC * NPIX];
__device__ float g_SM[CL * NPIX];         // f32 row-major (for conv)
__device__ float g_tmp[CL * NPIX];
__device__ float g_Fs[CL * NPIX];
__device__ float g_part[(size_t)KSPLIT * NPAD * NPIX];  // split-K partials [ks][r][p]
__device__ float g_As[CC * CC];           // compat @ Wsp
__device__ float g_Ab[CC * CC];           // compat @ Wbl
__device__ float g_epart[LL * NBE];

__device__ __forceinline__ void cp16(void* dst, const void* src) {
    unsigned d = (unsigned)__cvta_generic_to_shared(dst);
    asm volatile("cp.async.cg.shared.global [%0], [%1], 16;" :: "r"(d), "l"(src));
}
__device__ __forceinline__ void mma_fp8(float* d, uint a0, uint a1, uint a2, uint a3,
                                        uint b0, uint b1) {
    asm volatile(
        "mma.sync.aligned.m16n8k32.row.col.f32.e4m3.e4m3.f32 "
        "{%0,%1,%2,%3}, {%4,%5,%6,%7}, {%8,%9}, {%0,%1,%2,%3};"
        : "+f"(d[0]), "+f"(d[1]), "+f"(d[2]), "+f"(d[3])
        : "r"(a0), "r"(a1), "r"(a2), "r"(a3), "r"(b0), "r"(b1));
}
__device__ __forceinline__ void ldsm4(uint& r0, uint& r1, uint& r2, uint& r3, uint addr) {
    asm volatile("ldmatrix.sync.aligned.m8n8.x4.shared.b16 {%0,%1,%2,%3}, [%4];"
                 : "=r"(r0), "=r"(r1), "=r"(r2), "=r"(r3) : "r"(addr));
}
__device__ __forceinline__ void ldsm2(uint& r0, uint& r1, uint addr) {
    asm volatile("ldmatrix.sync.aligned.m8n8.x2.shared.b16 {%0,%1}, [%2];"
                 : "=r"(r0), "=r"(r1) : "r"(addr));
}
__device__ __forceinline__ ushort fp8x2(float hi, float lo) {
    ushort r;
    asm("cvt.rn.satfinite.e4m3x2.f32 %0, %1, %2;" : "=h"(r) : "f"(hi), "f"(lo));
    return r;
}
__device__ __forceinline__ float ex2(float x) {
    float r;
    asm("ex2.approx.f32 %0, %1;" : "=f"(r) : "f"(x));
    return r;
}

// ---- launch 1: prep: log2e-scaled coords + half-norms, unary transpose, iter-1 softmax ----
__global__ void k_prep(const float* __restrict__ unary, const float* __restrict__ feat) {
    int p = blockIdx.x * blockDim.x + threadIdx.x;
    if (p >= NPIX) return;
    int y = p / WW, x = p % WW;
    const float sc = 1.20112240878645f;          // sqrt(log2e)
    const float inva = sc / 8.0f;                // /theta_alpha
    const float invb = sc / 0.15f;               // /theta_beta
    float4 z;
    z.x = (float)y * inva;
    z.y = (float)x * inva;
    z.z = feat[p * 3 + 0] * invb;
    z.w = feat[p * 3 + 1] * invb;
    float z1 = feat[p * 3 + 2] * invb;
    g_z4[p] = z;
    g_z1[p] = z1;
    g_zh[p] = 0.5f * (z.x * z.x + z.y * z.y + z.z * z.z + z.w * z.w + z1 * z1);
    float q[CC], m = -1e30f;
#pragma unroll
    for (int c = 0; c < CC; c++) {
        q[c] = unary[p * CC + c];
        g_unary[c * NPIX + p] = q[c];
        m = fmaxf(m, q[c]);
    }
    float s = 0.f;
#pragma unroll
    for (int c = 0; c < CC; c++) { q[c] = __expf(q[c] - m); s += q[c]; }
    float inv = 1.0f / s;
#pragma unroll
    for (int l = 0; l < LL; l++)
#pragma unroll
        for (int c = 0; c < CC; c++) {
            float v = q[c] * inv;
            g_SM[(l * CC + c) * NPIX + p] = v;
            g_SM8[(l * CC + c) * NPIX + p] = __nv_fp8_e4m3(v * 256.0f);
        }
}

// ---- launch 2: 1D spatial kernel, row sums, fused CxC matrices ----
__global__ void k_prep_small(const float* __restrict__ compat,
                             const float* __restrict__ wsp,
                             const float* __restrict__ wbl) {
    int tid = threadIdx.x;
    for (int i = tid; i < HH * HH; i += blockDim.x) {
        int a = i / HH, b = i % HH;
        float d = (float)(a - b);
        g_G[i] = expf(-d * d * (1.0f / 18.0f));   // 2*theta_gamma^2 = 18
    }
    __syncthreads();
    if (tid < HH) {
        float s = 0.f;
        for (int b = 0; b < HH; b++) s += g_G[tid * HH + b];
        g_Snorm[tid] = s;
    }
    if (tid < CC * CC) {
        int i = tid / CC, j = tid % CC;
        float as = 0.f, ab = 0.f;
        for (int k = 0; k < CC; k++) {
            as += compat[i * CC + k] * wsp[k * CC + j];
            ab += compat[i * CC + k] * wbl[k * CC + j];
        }
        g_As[tid] = as;
        g_Ab[tid] = ab;
    }
}

// ---- launch 3: bilateral kernel via MUFU ex2, scale folded into exponent ----
__global__ __launch_bounds__(256) void k_Kb() {
    int i0 = blockIdx.x * RPB;
    __shared__ float4 s_z4[RPB];
    __shared__ float s_z1[RPB], s_zh[RPB];
    if (threadIdx.x < RPB) {
        s_z4[threadIdx.x] = g_z4[i0 + threadIdx.x];
        s_z1[threadIdx.x] = g_z1[i0 + threadIdx.x];
        s_zh[threadIdx.x] = g_zh[i0 + threadIdx.x] - 8.0f;   // -8: fold x256 into ex2
    }
    __syncthreads();
    float4 zi[RPB]; float zi1[RPB], ci[RPB];
#pragma unroll
    for (int r = 0; r < RPB; r++) { zi[r] = s_z4[r]; zi1[r] = s_z1[r]; ci[r] = s_zh[r]; }

    float sum[RPB];
#pragma unroll
    for (int r = 0; r < RPB; r++) sum[r] = 0.f;

    for (int j = threadIdx.x * 2; j < NPIX; j += 512) {
        float4 za = g_z4[j], zb = g_z4[j + 1];
        float z1a = g_z1[j], z1b = g_z1[j + 1];
        float ha = g_zh[j], hb = g_zh[j + 1];
#pragma unroll
        for (int r = 0; r < RPB; r++) {
            float dota = zi[r].x * za.x + zi[r].y * za.y + zi[r].z * za.z
                       + zi[r].w * za.w + zi1[r] * z1a;
            float dotb = zi[r].x * zb.x + zi[r].y * zb.y + zi[r].z * zb.z
                       + zi[r].w * zb.w + zi1[r] * z1b;
            float va = ex2(dota - ci[r] - ha);   // = 256 * exp(-d/2)
            float vb = ex2(dotb - ci[r] - hb);
            *(ushort*)&g_Kb8[(size_t)(i0 + r) * NPIX + j] = fp8x2(vb, va);
            sum[r] += va + vb;
        }
    }
#pragma unroll
    for (int r = 0; r < RPB; r++)
#pragma unroll
        for (int o = 16; o > 0; o >>= 1)
            sum[r] += __shfl_xor_sync(0xffffffffu, sum[r], o);
    __shared__ float wsum[8][RPB];
    int w = threadIdx.x >> 5, lane = threadIdx.x & 31;
    if (lane == 0)
#pragma unroll
        for (int r = 0; r < RPB; r++) wsum[w][r] = sum[r];
    __syncthreads();
    if (threadIdx.x < RPB) {
        float s = 0.f;
#pragma unroll
        for (int w2 = 0; w2 < 8; w2++) s += wsum[w2][threadIdx.x];
        g_normb[i0 + threadIdx.x] = s;           // scaled by 256
    }
}

// ---- launch 4 (captured): FP8 GEMM, MT=128, n=40 (2x ldsm4 + ldsm2), 2-stage ----
__global__ __launch_bounds__(256) void k_gemm() {
    extern __shared__ __align__(16) uchar smem[];
    uchar* As = smem;                        // [2][MT*KPB] bytes
    uchar* Bs = smem + 2 * MT * KPB;         // [2][NPAD*KPB] bytes

    int tid = threadIdx.x, lane = tid & 31, w = tid >> 5;
    int ptile = blockIdx.x * MT;
    int kbase = blockIdx.y * KPART;
    const uchar* Kb = (const uchar*)g_Kb8;
    const uchar* SMb = (const uchar*)g_SM8;

    float d[5][4];
#pragma unroll
    for (int f = 0; f < 5; f++)
#pragma unroll
        for (int j = 0; j < 4; j++) d[f][j] = 0.f;

    auto issue = [&](int bi, int k0) {
        uchar* dA = As + bi * (MT * KPB);
#pragma unroll 1
        for (int f = tid; f < 1024; f += 256) {   // 128 rows x 8 x 16B chunks
            int row = f >> 3, off = f & 7;
            cp16(&dA[row * KPB + off * 16],
                 Kb + (size_t)(ptile + row) * NPIX + k0 + off * 16);
        }
        uchar* dB = Bs + bi * (NPAD * KPB);
#pragma unroll 1
        for (int f = tid; f < 320; f += 256) {    // 40 rows x 8 x 16B chunks
            int row = f >> 3, off = f & 7;
            cp16(&dB[row * KPB + off * 16],
                 SMb + (size_t)row * NPIX + k0 + off * 16);
        }
    };

    issue(0, kbase);
    asm volatile("cp.async.commit_group;");
    issue(1, kbase + KSTAGE);
    asm volatile("cp.async.commit_group;");

    // ldmatrix lane-address offsets (bytes)
    uint offA = (w * 16 + (lane & 15)) * KPB + (lane >> 4) * 16;
    uint offB4[2];
#pragma unroll
    for (int f = 0; f < 2; f++)
        offB4[f] = (16 * f + (lane & 7) + ((lane >> 4) << 3)) * KPB + ((lane >> 3) & 1) * 16;
    uint offB2 = (32 + (lane & 7)) * KPB + ((lane >> 3) & 1) * 16;
    uint baseA = (uint)__cvta_generic_to_shared(As);
    uint baseB = (uint)__cvta_generic_to_shared(Bs);
    const uint strA = MT * KPB, strB = NPAD * KPB;

    for (int t = 0; t < NSTAGES; t++) {
        if (t + 1 < NSTAGES) {
            asm volatile("cp.async.wait_group 1;");
        } else {
            asm volatile("cp.async.wait_group 0;");
        }
        __syncthreads();
        int bi = t & 1;
        uint aP = baseA + bi * strA + offA;
        uint bP = baseB + bi * strB;
#pragma unroll
        for (int j = 0; j < 4; j++) {             // j covers 32 bytes of k
            uint a0, a1, a2, a3;
            ldsm4(a0, a1, a2, a3, aP + j * 32);
#pragma unroll
            for (int f = 0; f < 2; f++) {
                uint b0, b1, b2, b3;
                ldsm4(b0, b1, b2, b3, bP + offB4[f] + j * 32);
                mma_fp8(d[2 * f],     a0, a1, a2, a3, b0, b1);
                mma_fp8(d[2 * f + 1], a0, a1, a2, a3, b2, b3);
            }
            uint c0, c1;
            ldsm2(c0, c1, bP + offB2 + j * 32);
            mma_fp8(d[4], a0, a1, a2, a3, c0, c1);
        }
        __syncthreads();                          // all warps done with buf bi
        if (t + 2 < NSTAGES) {
            issue(bi, kbase + (t + 2) * KSTAGE);  // refill the freed buffer
            asm volatile("cp.async.commit_group;");
        }
    }

    // epilogue: D frag -> g_part[ks][r][p]
    int prow = ptile + w * 16 + (lane >> 2);
    size_t kb = (size_t)blockIdx.y * NPAD * NPIX;
#pragma unroll
    for (int f = 0; f < 5; f++) {
        int rc = f * 8 + (lane & 3) * 2;
        g_part[kb + (size_t)rc * NPIX + prow]           = d[f][0];
        g_part[kb + (size_t)(rc + 1) * NPIX + prow]     = d[f][1];
        g_part[kb + (size_t)rc * NPIX + prow + 8]       = d[f][2];
        g_part[kb + (size_t)(rc + 1) * NPIX + prow + 8] = d[f][3];
    }
}

// ---- separable spatial filter, split for full-chip parallelism ----
__global__ void k_conv_x() {
    int r = blockIdx.x / HH, y = blockIdx.x % HH;
    int x2 = threadIdx.x;
    __shared__ float row[WW];
    row[x2] = g_SM[r * NPIX + y * WW + x2];
    __syncthreads();
    float acc = 0.f;
#pragma unroll 8
    for (int x = 0; x < WW; x++) acc += row[x] * g_G[x * HH + x2];
    g_tmp[r * NPIX + y * WW + x2] = acc;
}

__global__ void k_conv_y() {
    int r = blockIdx.x / HH, y2 = blockIdx.x % HH;
    int x = threadIdx.x;
    float acc = 0.f;
#pragma unroll 8
    for (int y = 0; y < HH; y++)
        acc += g_tmp[r * NPIX + y * WW + x] * g_G[y * HH + y2];
    g_Fs[r * NPIX + y2 * WW + x] = acc / (g_Snorm[y2] * g_Snorm[x]);
}

// ---- fused: split-K reduce + unscale + normalize + q update + softmax ----
__global__ void k_post(const float* __restrict__ lg) {
    int t = blockIdx.x * 256 + threadIdx.x;
    if (t >= LL * NPIX) return;
    int l = t / NPIX, p = t % NPIX;
    float invnb = INV256 / g_normb[p];
    float fs[CC], fb[CC];
#pragma unroll
    for (int c = 0; c < CC; c++) {
        int r = l * CC + c;
        fs[c] = g_Fs[r * NPIX + p];
        float s = 0.f;
#pragma unroll
        for (int ks = 0; ks < KSPLIT; ks++)
            s += g_part[(size_t)ks * NPAD * NPIX + (size_t)r * NPIX + p];
        fb[c] = s * invnb;
    }
    float q[CC], m = -1e30f;
#pragma unroll
    for (int c = 0; c < CC; c++) {
        float pw = 0.f;
#pragma unroll
        for (int k = 0; k < CC; k++)
            pw += g_As[c * CC + k] * fs[k] + g_Ab[c * CC + k] * fb[k];
        q[c] = g_unary[c * NPIX + p] + lg[c * CC + l] - pw;
        m = fmaxf(m, q[c]);
    }
    float s = 0.f;
#pragma unroll
    for (int c = 0; c < CC; c++) { q[c] = __expf(q[c] - m); s += q[c]; }
    float inv = 1.0f / s;
#pragma unroll
    for (int c = 0; c < CC; c++) {
        float v = q[c] * inv;
        g_SM[(l * CC + c) * NPIX + p] = v;
        g_SM8[(l * CC + c) * NPIX + p] = __nv_fp8_e4m3(v * 256.0f);
    }
}

// ---- ELBO partials: grid (25, LL), one pixel per thread ----
__global__ void k_elbo(const float* __restrict__ wsp,
                       const float* __restrict__ wbl,
                       const float* __restrict__ lg) {
    int l = blockIdx.y;
    int p = blockIdx.x * 256 + threadIdx.x;   // 25*256 = NPIX exact
    float acc;
    {
        float invnb = INV256 / g_normb[p];
        float sm[CC], fs[CC], fb[CC];
#pragma unroll
        for (int c = 0; c < CC; c++) {
            int r = l * CC + c;
            sm[c] = g_SM[r * NPIX + p];
            fs[c] = g_Fs[r * NPIX + p];
            float s = 0.f;
#pragma unroll
            for (int ks = 0; ks < KSPLIT; ks++)
                s += g_part[(size_t)ks * NPAD * NPIX + (size_t)r * NPIX + p];
            fb[c] = s * invnb;
        }
        acc = 0.f;
#pragma unroll
        for (int c = 0; c < CC; c++) {
            float msg = 0.f;
#pragma unroll
            for (int k = 0; k < CC; k++)
                msg += wsp[c * CC + k] * fs[k] + wbl[c * CC + k] * fb[k];
            acc += sm[c] * (g_unary[c * NPIX + p] + lg[c * CC + l] - msg)
                 - sm[c] * logf(sm[c] + 1e-10f);
        }
    }
    __shared__ float red[256];
    red[threadIdx.x] = acc;
    __syncthreads();
    for (int s = 128; s > 0; s >>= 1) {
        if (threadIdx.x < s) red[threadIdx.x] += red[threadIdx.x + s];
        __syncthreads();
    }
    if (threadIdx.x == 0) g_epart[l * NBE + blockIdx.x] = red[0];
}

__global__ void k_final(float* __restrict__ out) {
    int l = threadIdx.x;
    if (l < LL) {
        float s = 0.f;
        for (int b = 0; b < NBE; b++) s += g_epart[l * NBE + b];
        out[l] = s;
    }
}

extern "C" void kernel_launch(void* const* d_in, const int* in_sizes, int n_in,
                              void* d_out, int out_size) {
    const float* unary  = (const float*)d_in[0];   // (1,80,80,6)
    const float* feat   = (const float*)d_in[1];   // (80,80,3)
    const float* compat = (const float*)d_in[2];   // (6,6)
    const float* lg     = (const float*)d_in[3];   // (6,6)
    const float* wsp    = (const float*)d_in[4];   // (6,6)
    const float* wbl    = (const float*)d_in[5];   // (6,6)
    float* out = (float*)d_out;

    cudaFuncSetAttribute(k_gemm, cudaFuncAttributeMaxDynamicSharedMemorySize, GEMM_SMEM);

    // launches 1-4: slot 4 = the NPAD-40 gemm -> gets the ncu capture
    k_prep<<<25, 256>>>(unary, feat);
    k_prep_small<<<1, 128>>>(compat, wsp, wbl);
    k_Kb<<<NPIX / RPB, 256>>>();
    k_gemm<<<dim3(NPIX / MT, KSPLIT), 256, GEMM_SMEM>>>();   // CAPTURED

    k_conv_x<<<CL * HH, WW>>>();
    k_conv_y<<<CL * HH, WW>>>();

    // passes 2..5
    for (int it = 0; it < 4; it++) {
        k_post<<<150, 256>>>(lg);
        k_conv_x<<<CL * HH, WW>>>();
        k_conv_y<<<CL * HH, WW>>>();
        k_gemm<<<dim3(NPIX / MT, KSPLIT), 256, GEMM_SMEM>>>();
    }

    k_elbo<<<dim3(NBE, LL), 256>>>(wsp, wbl, lg);
    k_final<<<1, 32>>>(out);
}

// round 17
// speedup vs baseline: 1.8019x; 1.1480x over previous
#include <cuda_runtime.h>
#include <cuda_bf16.h>
#include <cuda_fp8.h>
#include <math.h>

#define HH 80
#define WW 80
#define NPIX 6400
#define CC 6
#define LL 6
#define CL 36          // LL*CC
#define NPAD 40        // CL padded to 5x n8
#define MT 128         // gemm M-tile (rows of Kb)
#define KSPLIT 10
#define KPART 640      // NPIX/KSPLIT
#define KSTAGE 128     // fp8 elems per stage
#define NSTAGES 5      // KPART/KSTAGE
#define KPB 144        // padded BYTES per smem row (bank-conflict-free)
#define NBE 25         // elbo partial blocks per label
#define RPB 8          // k_Kb rows per block
#define GEMM_SMEM (2 * (MT + NPAD) * KPB)   // 48384 B
// Kb stored as 256*exp(-d/2) (scale folded into exponent). sm8 = 256*sm.
#define INV256 (1.0f / 256.0f)

typedef unsigned long long ull;
typedef unsigned int uint;
typedef unsigned short ushort;
typedef unsigned char uchar;

// ---- scratch (device globals: allocation-free rule; zero-initialized) ----
__device__ __align__(16) __nv_fp8_e4m3 g_Kb8[(size_t)NPIX * NPIX];  // 41 MB bilateral kernel, fp8 (x256)
__device__ __align__(16) __nv_fp8_e4m3 g_SM8[NPAD * NPIX];          // softmax rows fp8 (x256; rows 36..39 stay 0)
__device__ float g_normb[NPIX];           // scaled by 256
__device__ float g_G[HH * HH];            // 1D spatial gaussian (theta_gamma)
__device__ float g_Snorm[HH];
__device__ float4 g_z4[NPIX];             // coords scaled by sqrt(log2e)/theta
__device__ float  g_z1[NPIX];
__device__ float  g_zh[NPIX];             // 0.5*|z'|^2
__device__ float g_unary[CC * NPIX];
__device__ float g_SM[CL * NPIX];         // f32 row-major (for conv)
__device__ float g_tmp[CL * NPIX];
__device__ float g_Fs[CL * NPIX];
__device__ float g_part[(size_t)KSPLIT * NPAD * NPIX];  // split-K partials [ks][r][p]
__device__ float g_As[CC * CC];           // compat @ Wsp
__device__ float g_Ab[CC * CC];           // compat @ Wbl
__device__ float g_epart[LL * NBE];

__device__ __forceinline__ void cp16(void* dst, const void* src) {
    unsigned d = (unsigned)__cvta_generic_to_shared(dst);
    asm volatile("cp.async.cg.shared.global [%0], [%1], 16;" :: "r"(d), "l"(src));
}
__device__ __forceinline__ void mma_fp8(float* d, uint a0, uint a1, uint a2, uint a3,
                                        uint b0, uint b1) {
    asm volatile(
        "mma.sync.aligned.m16n8k32.row.col.f32.e4m3.e4m3.f32 "
        "{%0,%1,%2,%3}, {%4,%5,%6,%7}, {%8,%9}, {%0,%1,%2,%3};"
        : "+f"(d[0]), "+f"(d[1]), "+f"(d[2]), "+f"(d[3])
        : "r"(a0), "r"(a1), "r"(a2), "r"(a3), "r"(b0), "r"(b1));
}
__device__ __forceinline__ void ldsm4(uint& r0, uint& r1, uint& r2, uint& r3, uint addr) {
    asm volatile("ldmatrix.sync.aligned.m8n8.x4.shared.b16 {%0,%1,%2,%3}, [%4];"
                 : "=r"(r0), "=r"(r1), "=r"(r2), "=r"(r3) : "r"(addr));
}
__device__ __forceinline__ void ldsm2(uint& r0, uint& r1, uint addr) {
    asm volatile("ldmatrix.sync.aligned.m8n8.x2.shared.b16 {%0,%1}, [%2];"
                 : "=r"(r0), "=r"(r1) : "r"(addr));
}
__device__ __forceinline__ ushort fp8x2(float hi, float lo) {
    ushort r;
    asm("cvt.rn.satfinite.e4m3x2.f32 %0, %1, %2;" : "=h"(r) : "f"(hi), "f"(lo));
    return r;
}
__device__ __forceinline__ float ex2(float x) {
    float r;
    asm("ex2.approx.f32 %0, %1;" : "=f"(r) : "f"(x));
    return r;
}

// ---- prep: log2e-scaled coords + half-norms, unary transpose, iter-1 softmax ----
__global__ void k_prep(const float* __restrict__ unary, const float* __restrict__ feat) {
    int p = blockIdx.x * blockDim.x + threadIdx.x;
    if (p >= NPIX) return;
    int y = p / WW, x = p % WW;
    const float sc = 1.20112240878645f;          // sqrt(log2e)
    const float inva = sc / 8.0f;                // /theta_alpha
    const float invb = sc / 0.15f;               // /theta_beta
    float4 z;
    z.x = (float)y * inva;
    z.y = (float)x * inva;
    z.z = feat[p * 3 + 0] * invb;
    z.w = feat[p * 3 + 1] * invb;
    float z1 = feat[p * 3 + 2] * invb;
    g_z4[p] = z;
    g_z1[p] = z1;
    g_zh[p] = 0.5f * (z.x * z.x + z.y * z.y + z.z * z.z + z.w * z.w + z1 * z1);
    float q[CC], m = -1e30f;
#pragma unroll
    for (int c = 0; c < CC; c++) {
        q[c] = unary[p * CC + c];
        g_unary[c * NPIX + p] = q[c];
        m = fmaxf(m, q[c]);
    }
    float s = 0.f;
#pragma unroll
    for (int c = 0; c < CC; c++) { q[c] = __expf(q[c] - m); s += q[c]; }
    float inv = 1.0f / s;
#pragma unroll
    for (int l = 0; l < LL; l++)
#pragma unroll
        for (int c = 0; c < CC; c++) {
            float v = q[c] * inv;
            g_SM[(l * CC + c) * NPIX + p] = v;
            g_SM8[(l * CC + c) * NPIX + p] = __nv_fp8_e4m3(v * 256.0f);
        }
}

// ---- 1D spatial kernel, row sums, fused CxC matrices ----
__global__ void k_prep_small(const float* __restrict__ compat,
                             const float* __restrict__ wsp,
                             const float* __restrict__ wbl) {
    int tid = threadIdx.x;
    for (int i = tid; i < HH * HH; i += blockDim.x) {
        int a = i / HH, b = i % HH;
        float d = (float)(a - b);
        g_G[i] = expf(-d * d * (1.0f / 18.0f));   // 2*theta_gamma^2 = 18
    }
    __syncthreads();
    if (tid < HH) {
        float s = 0.f;
        for (int b = 0; b < HH; b++) s += g_G[tid * HH + b];
        g_Snorm[tid] = s;
    }
    if (tid < CC * CC) {
        int i = tid / CC, j = tid % CC;
        float as = 0.f, ab = 0.f;
        for (int k = 0; k < CC; k++) {
            as += compat[i * CC + k] * wsp[k * CC + j];
            ab += compat[i * CC + k] * wbl[k * CC + j];
        }
        g_As[tid] = as;
        g_Ab[tid] = ab;
    }
}

// ---- bilateral kernel via MUFU ex2, scale folded into exponent ----
__global__ __launch_bounds__(256) void k_Kb() {
    int i0 = blockIdx.x * RPB;
    __shared__ float4 s_z4[RPB];
    __shared__ float s_z1[RPB], s_zh[RPB];
    if (threadIdx.x < RPB) {
        s_z4[threadIdx.x] = g_z4[i0 + threadIdx.x];
        s_z1[threadIdx.x] = g_z1[i0 + threadIdx.x];
        s_zh[threadIdx.x] = g_zh[i0 + threadIdx.x] - 8.0f;   // -8: fold x256 into ex2
    }
    __syncthreads();
    float4 zi[RPB]; float zi1[RPB], ci[RPB];
#pragma unroll
    for (int r = 0; r < RPB; r++) { zi[r] = s_z4[r]; zi1[r] = s_z1[r]; ci[r] = s_zh[r]; }

    float sum[RPB];
#pragma unroll
    for (int r = 0; r < RPB; r++) sum[r] = 0.f;

    for (int j = threadIdx.x * 2; j < NPIX; j += 512) {
        float4 za = g_z4[j], zb = g_z4[j + 1];
        float z1a = g_z1[j], z1b = g_z1[j + 1];
        float ha = g_zh[j], hb = g_zh[j + 1];
#pragma unroll
        for (int r = 0; r < RPB; r++) {
            float dota = zi[r].x * za.x + zi[r].y * za.y + zi[r].z * za.z
                       + zi[r].w * za.w + zi1[r] * z1a;
            float dotb = zi[r].x * zb.x + zi[r].y * zb.y + zi[r].z * zb.z
                       + zi[r].w * zb.w + zi1[r] * z1b;
            float va = ex2(dota - ci[r] - ha);   // = 256 * exp(-d/2)
            float vb = ex2(dotb - ci[r] - hb);
            *(ushort*)&g_Kb8[(size_t)(i0 + r) * NPIX + j] = fp8x2(vb, va);
            sum[r] += va + vb;
        }
    }
#pragma unroll
    for (int r = 0; r < RPB; r++)
#pragma unroll
        for (int o = 16; o > 0; o >>= 1)
            sum[r] += __shfl_xor_sync(0xffffffffu, sum[r], o);
    __shared__ float wsum[8][RPB];
    int w = threadIdx.x >> 5, lane = threadIdx.x & 31;
    if (lane == 0)
#pragma unroll
        for (int r = 0; r < RPB; r++) wsum[w][r] = sum[r];
    __syncthreads();
    if (threadIdx.x < RPB) {
        float s = 0.f;
#pragma unroll
        for (int w2 = 0; w2 < 8; w2++) s += wsum[w2][threadIdx.x];
        g_normb[i0 + threadIdx.x] = s;           // scaled by 256
    }
}

// ---- FP8 GEMM, MT=128, n=40, 2-stage cp.async, hoisted addresses ----
__global__ __launch_bounds__(256) void k_gemm() {
    extern __shared__ __align__(16) uchar smem[];
    uchar* As = smem;                        // [2][MT*KPB] bytes
    uchar* Bs = smem + 2 * MT * KPB;         // [2][NPAD*KPB] bytes

    int tid = threadIdx.x, lane = tid & 31, w = tid >> 5;
    int ptile = blockIdx.x * MT;
    int kbase = blockIdx.y * KPART;

    // hoisted cp.async addresses: 4 A-chunks + 1-2 B-chunks per thread
    const uchar* asrc[4];
    uint adst[4];
#pragma unroll
    for (int c = 0; c < 4; c++) {
        int f = c * 256 + tid, row = f >> 3, off = (f & 7) * 16;
        asrc[c] = (const uchar*)g_Kb8 + (size_t)(ptile + row) * NPIX + kbase + off;
        adst[c] = row * KPB + off;
    }
    const uchar* bsrc0 = (const uchar*)g_SM8 + (size_t)(tid >> 3) * NPIX + kbase + (tid & 7) * 16;
    uint bdst0 = (tid >> 3) * KPB + (tid & 7) * 16;
    const uchar* bsrc1 = (const uchar*)g_SM8 + (size_t)((tid + 256) >> 3) * NPIX + kbase + (tid & 7) * 16;
    uint bdst1 = ((tid + 256) >> 3) * KPB + (tid & 7) * 16;

    float d[5][4];
#pragma unroll
    for (int f = 0; f < 5; f++)
#pragma unroll
        for (int j = 0; j < 4; j++) d[f][j] = 0.f;

    const uint strA = MT * KPB, strB = NPAD * KPB;
    auto issue = [&](int bi, int koff) {
        uchar* dA = As + bi * strA;
#pragma unroll
        for (int c = 0; c < 4; c++)
            cp16(dA + adst[c], asrc[c] + koff);
        uchar* dB = Bs + bi * strB;
        cp16(dB + bdst0, bsrc0 + koff);
        if (tid < 64) cp16(dB + bdst1, bsrc1 + koff);
    };

    issue(0, 0);
    asm volatile("cp.async.commit_group;");
    issue(1, KSTAGE);
    asm volatile("cp.async.commit_group;");

    // ldmatrix lane-address offsets (bytes)
    uint offA = (w * 16 + (lane & 15)) * KPB + (lane >> 4) * 16;
    uint offB4[2];
#pragma unroll
    for (int f = 0; f < 2; f++)
        offB4[f] = (16 * f + (lane & 7) + ((lane >> 4) << 3)) * KPB + ((lane >> 3) & 1) * 16;
    uint offB2 = (32 + (lane & 7)) * KPB + ((lane >> 3) & 1) * 16;
    uint baseA = (uint)__cvta_generic_to_shared(As);
    uint baseB = (uint)__cvta_generic_to_shared(Bs);

    for (int t = 0; t < NSTAGES; t++) {
        if (t + 1 < NSTAGES) {
            asm volatile("cp.async.wait_group 1;");
        } else {
            asm volatile("cp.async.wait_group 0;");
        }
        __syncthreads();
        int bi = t & 1;
        uint aP = baseA + bi * strA + offA;
        uint bP = baseB + bi * strB;
#pragma unroll
        for (int j = 0; j < 4; j++) {             // j covers 32 bytes of k
            uint a0, a1, a2, a3;
            ldsm4(a0, a1, a2, a3, aP + j * 32);
#pragma unroll
            for (int f = 0; f < 2; f++) {
                uint b0, b1, b2, b3;
                ldsm4(b0, b1, b2, b3, bP + offB4[f] + j * 32);
                mma_fp8(d[2 * f],     a0, a1, a2, a3, b0, b1);
                mma_fp8(d[2 * f + 1], a0, a1, a2, a3, b2, b3);
            }
            uint c0, c1;
            ldsm2(c0, c1, bP + offB2 + j * 32);
            mma_fp8(d[4], a0, a1, a2, a3, c0, c1);
        }
        __syncthreads();                          // all warps done with buf bi
        if (t + 2 < NSTAGES) {
            issue(bi, (t + 2) * KSTAGE);          // refill the freed buffer
            asm volatile("cp.async.commit_group;");
        }
    }

    // epilogue: D frag -> g_part[ks][r][p]
    int prow = ptile + w * 16 + (lane >> 2);
    size_t kb = (size_t)blockIdx.y * NPAD * NPIX;
#pragma unroll
    for (int f = 0; f < 5; f++) {
        int rc = f * 8 + (lane & 3) * 2;
        g_part[kb + (size_t)rc * NPIX + prow]           = d[f][0];
        g_part[kb + (size_t)(rc + 1) * NPIX + prow]     = d[f][1];
        g_part[kb + (size_t)rc * NPIX + prow + 8]       = d[f][2];
        g_part[kb + (size_t)(rc + 1) * NPIX + prow + 8] = d[f][3];
    }
}

// ---- separable spatial filter, split for full-chip parallelism ----
__global__ void k_conv_x() {
    int r = blockIdx.x / HH, y = blockIdx.x % HH;
    int x2 = threadIdx.x;
    __shared__ float row[WW];
    row[x2] = g_SM[r * NPIX + y * WW + x2];
    __syncthreads();
    float acc = 0.f;
#pragma unroll 8
    for (int x = 0; x < WW; x++) acc += row[x] * g_G[x * HH + x2];
    g_tmp[r * NPIX + y * WW + x2] = acc;
}

__global__ void k_conv_y() {
    int r = blockIdx.x / HH, y2 = blockIdx.x % HH;
    int x = threadIdx.x;
    float acc = 0.f;
#pragma unroll 8
    for (int y = 0; y < HH; y++)
        acc += g_tmp[r * NPIX + y * WW + x] * g_G[y * HH + y2];
    g_Fs[r * NPIX + y2 * WW + x] = acc / (g_Snorm[y2] * g_Snorm[x]);
}

// ---- fused: split-K reduce + unscale + normalize + q update + softmax ----
__global__ void k_post(const float* __restrict__ lg) {
    int t = blockIdx.x * 256 + threadIdx.x;
    if (t >= LL * NPIX) return;
    int l = t / NPIX, p = t % NPIX;
    float invnb = INV256 / g_normb[p];
    float fs[CC], fb[CC];
#pragma unroll
    for (int c = 0; c < CC; c++) {
        int r = l * CC + c;
        fs[c] = g_Fs[r * NPIX + p];
        float s = 0.f;
#pragma unroll
        for (int ks = 0; ks < KSPLIT; ks++)
            s += g_part[(size_t)ks * NPAD * NPIX + (size_t)r * NPIX + p];
        fb[c] = s * invnb;
    }
    float q[CC], m = -1e30f;
#pragma unroll
    for (int c = 0; c < CC; c++) {
        float pw = 0.f;
#pragma unroll
        for (int k = 0; k < CC; k++)
            pw += g_As[c * CC + k] * fs[k] + g_Ab[c * CC + k] * fb[k];
        q[c] = g_unary[c * NPIX + p] + lg[c * CC + l] - pw;
        m = fmaxf(m, q[c]);
    }
    float s = 0.f;
#pragma unroll
    for (int c = 0; c < CC; c++) { q[c] = __expf(q[c] - m); s += q[c]; }
    float inv = 1.0f / s;
#pragma unroll
    for (int c = 0; c < CC; c++) {
        float v = q[c] * inv;
        g_SM[(l * CC + c) * NPIX + p] = v;
        g_SM8[(l * CC + c) * NPIX + p] = __nv_fp8_e4m3(v * 256.0f);
    }
}

// ---- ELBO partials: grid (25, LL), one pixel per thread ----
__global__ void k_elbo(const float* __restrict__ wsp,
                       const float* __restrict__ wbl,
                       const float* __restrict__ lg) {
    int l = blockIdx.y;
    int p = blockIdx.x * 256 + threadIdx.x;   // 25*256 = NPIX exact
    float acc;
    {
        float invnb = INV256 / g_normb[p];
        float sm[CC], fs[CC], fb[CC];
#pragma unroll
        for (int c = 0; c < CC; c++) {
            int r = l * CC + c;
            sm[c] = g_SM[r * NPIX + p];
            fs[c] = g_Fs[r * NPIX + p];
            float s = 0.f;
#pragma unroll
            for (int ks = 0; ks < KSPLIT; ks++)
                s += g_part[(size_t)ks * NPAD * NPIX + (size_t)r * NPIX + p];
            fb[c] = s * invnb;
        }
        acc = 0.f;
#pragma unroll
        for (int c = 0; c < CC; c++) {
            float msg = 0.f;
#pragma unroll
            for (int k = 0; k < CC; k++)
                msg += wsp[c * CC + k] * fs[k] + wbl[c * CC + k] * fb[k];
            acc += sm[c] * (g_unary[c * NPIX + p] + lg[c * CC + l] - msg)
                 - sm[c] * logf(sm[c] + 1e-10f);
        }
    }
    __shared__ float red[256];
    red[threadIdx.x] = acc;
    __syncthreads();
    for (int s = 128; s > 0; s >>= 1) {
        if (threadIdx.x < s) red[threadIdx.x] += red[threadIdx.x + s];
        __syncthreads();
    }
    if (threadIdx.x == 0) g_epart[l * NBE + blockIdx.x] = red[0];
}

__global__ void k_final(float* __restrict__ out) {
    int l = threadIdx.x;
    if (l < LL) {
        float s = 0.f;
        for (int b = 0; b < NBE; b++) s += g_epart[l * NBE + b];
        out[l] = s;
    }
}

extern "C" void kernel_launch(void* const* d_in, const int* in_sizes, int n_in,
                              void* d_out, int out_size) {
    const float* unary  = (const float*)d_in[0];   // (1,80,80,6)
    const float* feat   = (const float*)d_in[1];   // (80,80,3)
    const float* compat = (const float*)d_in[2];   // (6,6)
    const float* lg     = (const float*)d_in[3];   // (6,6)
    const float* wsp    = (const float*)d_in[4];   // (6,6)
    const float* wbl    = (const float*)d_in[5];   // (6,6)
    float* out = (float*)d_out;

    // side stream + events, created once on the (uncaptured) correctness run
    static cudaStream_t s1 = nullptr;
    static cudaEvent_t ev[12];
    if (!s1) {
        cudaStreamCreateWithFlags(&s1, cudaStreamNonBlocking);
        for (int i = 0; i < 12; i++)
            cudaEventCreateWithFlags(&ev[i], cudaEventDisableTiming);
        cudaFuncSetAttribute(k_gemm, cudaFuncAttributeMaxDynamicSharedMemorySize, GEMM_SMEM);
    }

    // main stream: prep -> Kb -> gemm ... ; side stream: tables + spatial conv
    k_prep<<<25, 256>>>(unary, feat);                        // 1
    cudaEventRecord(ev[0], 0);
    cudaStreamWaitEvent(s1, ev[0], 0);
    k_Kb<<<NPIX / RPB, 256>>>();                             // 2
    k_prep_small<<<1, 128, 0, s1>>>(compat, wsp, wbl);       // 3 (side)
    k_gemm<<<dim3(NPIX / MT, KSPLIT), 256, GEMM_SMEM>>>();   // 4 CAPTURED
    k_conv_x<<<CL * HH, WW, 0, s1>>>();                      // side
    k_conv_y<<<CL * HH, WW, 0, s1>>>();                      // side
    cudaEventRecord(ev[1], s1);
    cudaStreamWaitEvent(0, ev[1], 0);

    // passes 2..5: conv chain on s1 overlaps gemm on main
    for (int it = 0; it < 4; it++) {
        k_post<<<150, 256>>>(lg);
        cudaEventRecord(ev[2 + 2 * it], 0);
        cudaStreamWaitEvent(s1, ev[2 + 2 * it], 0);
        k_gemm<<<dim3(NPIX / MT, KSPLIT), 256, GEMM_SMEM>>>();
        k_conv_x<<<CL * HH, WW, 0, s1>>>();
        k_conv_y<<<CL * HH, WW, 0, s1>>>();
        cudaEventRecord(ev[3 + 2 * it], s1);
        cudaStreamWaitEvent(0, ev[3 + 2 * it], 0);
    }

    k_elbo<<<dim3(NBE, LL), 256>>>(wsp, wbl, lg);
    k_final<<<1, 32>>>(out);
}